// round 14
// baseline (speedup 1.0000x reference)
#include <cuda_runtime.h>
#include <cuda_bf16.h>
#include <math.h>
#include <stdint.h>

#define NN 2048
#define DM 256
#define NP1 2049
#define NORMC (-8.317766166719343f)
#define LOGN (7.624618986159398f)
#define LOG4096 (8.317766166719343f)
#define SZ ((size_t)NN*DM)
#define HSZ ((size_t)NN*512)
typedef __nv_bfloat16 bf;

// ---------- static scratch ----------
__device__ float g_xF[2*SZ], g_hf[2*HSZ];
__device__ bf g_yh[2*HSZ], g_yl[2*HSZ];
__device__ bf g_qh[2*SZ], g_ql[2*SZ], g_kh[2*SZ], g_kl[2*SZ];
__device__ bf g_vh[2*SZ], g_vl[2*SZ], g_aoh[2*SZ], g_aol[2*SZ];
__device__ bf g_hh[2*HSZ], g_hl[2*HSZ];
__device__ bf g_wqh[30*65536], g_wql[30*65536], g_wmh[10*65536], g_wml[10*65536];
__device__ bf g_w1h[10*262144], g_w1l[10*262144], g_w2h[10*131072], g_w2l[10*131072];
__device__ bf g_fph[65536], g_fpl[65536];
__device__ float g_pbp[30*256];
__device__ float g_cs[4*NN*32];
__device__ float g_bnS[2*16*512], g_bnQ[2*16*512];
__device__ float g_u[NP1], g_vv[NP1], g_pm[16*NP1], g_ps[16*NP1];
__device__ int   g_cnt[16];          // zero-initialized; reset by combiner each use

// ---------- HMMA m16n8k16 bf16 + ldmatrix ----------
__device__ __forceinline__ void mma16816(float* c, const uint32_t* a, const uint32_t* b) {
    asm volatile("mma.sync.aligned.m16n8k16.row.col.f32.bf16.bf16.f32 "
        "{%0,%1,%2,%3}, {%4,%5,%6,%7}, {%8,%9}, {%0,%1,%2,%3};"
        : "+f"(c[0]), "+f"(c[1]), "+f"(c[2]), "+f"(c[3])
        : "r"(a[0]), "r"(a[1]), "r"(a[2]), "r"(a[3]), "r"(b[0]), "r"(b[1]));
}
__device__ __forceinline__ void ldsm4(uint32_t& r0, uint32_t& r1, uint32_t& r2, uint32_t& r3,
                                      uint32_t addr) {
    asm volatile("ldmatrix.sync.aligned.m8n8.x4.shared.b16 {%0,%1,%2,%3}, [%4];"
        : "=r"(r0), "=r"(r1), "=r"(r2), "=r"(r3) : "r"(addr));
}
#define CP16(dst, src) asm volatile("cp.async.ca.shared.global [%0], [%1], 16;" :: "r"(dst), "l"(src))

__device__ __forceinline__ uint32_t pkbf(float x, float y) {
    __nv_bfloat162 t = __floats2bfloat162_rn(x, y);
    return *(uint32_t*)&t;
}
__device__ __forceinline__ void split2(float x, float y, uint32_t& hi, uint32_t& lo) {
    bf hx = __float2bfloat16(x), hy = __float2bfloat16(y);
    __nv_bfloat162 hp; hp.x = hx; hp.y = hy;
    hi = *(uint32_t*)&hp;
    lo = pkbf(x - __bfloat162float(hx), y - __bfloat162float(hy));
}

// ---------- generic split-bf16 HMMA GEMM (R10/R13: 2-stage cp.async) ----------
struct MZ { const bf *Ah,*Al,*Bh,*Bl; const float *bias,*res; float *outF; bf *oh,*ol;
            const float *cosv,*sinv; };
struct MArgs { MZ z[8]; int lda,ldb,ldo,ldh,K,Nc,bias_rows; float scale; };

#define APAD 72
#define AST (128*APAD)

template<int JT>
__global__ void __launch_bounds__(256) mma_gemm(MArgs a) {
    constexpr int CTAC = 32*JT;
    constexpr int BST = CTAC*APAD;
    constexpr int STAGE = 2*AST + 2*BST;
    extern __shared__ bf smem[];
    MZ z = a.z[blockIdx.z];
    int t = threadIdx.x, w = t>>5, lane = t&31;
    int wm = w & 1, wn = w >> 1;
    int row0 = blockIdx.x*128, col0 = blockIdx.y*CTAC;
    uint32_t smb = (uint32_t)__cvta_generic_to_shared(smem);
    int lr = t >> 3, lc = (t & 7) * 8;
    int nch = a.K >> 6;

    auto issue = [&](int ch, int st) {
        uint32_t base = smb + (uint32_t)(st*STAGE*2);
        const bf* Agh = z.Ah + (size_t)(row0+lr)*a.lda + ch*64 + lc;
        const bf* Agl = z.Al + (size_t)(row0+lr)*a.lda + ch*64 + lc;
        #pragma unroll
        for (int it=0; it<4; it++) {
            uint32_t d = base + (uint32_t)(((lr+it*32)*APAD + lc)*2);
            CP16(d,           Agh + (size_t)it*32*a.lda);
            CP16(d + AST*2,   Agl + (size_t)it*32*a.lda);
        }
        uint32_t bb = base + 2*AST*2;
        #pragma unroll
        for (int it=0; it<JT; it++) {
            int r = lr + it*32;
            if (col0 + r < a.Nc) {
                uint32_t d = bb + (uint32_t)((r*APAD + lc)*2);
                CP16(d,         z.Bh + (size_t)(col0+r)*a.ldb + ch*64 + lc);
                CP16(d + BST*2, z.Bl + (size_t)(col0+r)*a.ldb + ch*64 + lc);
            }
        }
        asm volatile("cp.async.commit_group;");
    };

    float acc[4][JT][4] = {};
    issue(0, 0);
    for (int ch = 0; ch < nch; ch++) {
        int st = ch & 1;
        if (ch + 1 < nch) {
            issue(ch+1, st^1);
            asm volatile("cp.async.wait_group 1;");
        } else {
            asm volatile("cp.async.wait_group 0;");
        }
        __syncthreads();
        uint32_t bAh = smb + (uint32_t)(st*STAGE*2);
        uint32_t bAl = bAh + AST*2;
        uint32_t bBh = bAh + 2*AST*2;
        uint32_t bBl = bBh + BST*2;
        int l15 = lane & 15, lhi = (lane >> 4)*8;
        #pragma unroll
        for (int ks = 0; ks < 4; ks++) {
            uint32_t Afh[4][4], Afl[4][4], Bfh[JT][2], Bfl[JT][2];
            uint32_t aoff = (uint32_t)(((wm*64 + l15)*APAD + ks*16 + lhi)*2);
            #pragma unroll
            for (int i = 0; i < 4; i++) {
                ldsm4(Afh[i][0],Afh[i][1],Afh[i][2],Afh[i][3], bAh + aoff + (uint32_t)(i*16*APAD*2));
                ldsm4(Afl[i][0],Afl[i][1],Afl[i][2],Afl[i][3], bAl + aoff + (uint32_t)(i*16*APAD*2));
            }
            #pragma unroll
            for (int j = 0; j < JT; j += 2) {
                uint32_t boff = (uint32_t)(((wn*8*JT + j*8 + l15)*APAD + ks*16 + lhi)*2);
                ldsm4(Bfh[j][0],Bfh[j+1][0],Bfh[j][1],Bfh[j+1][1], bBh + boff);
                ldsm4(Bfl[j][0],Bfl[j+1][0],Bfl[j][1],Bfl[j+1][1], bBl + boff);
            }
            #pragma unroll
            for (int i = 0; i < 4; i++)
                #pragma unroll
                for (int j = 0; j < JT; j++) {
                    mma16816(acc[i][j], Afh[i], Bfh[j]);
                    mma16816(acc[i][j], Afh[i], Bfl[j]);
                    mma16816(acc[i][j], Afl[i], Bfh[j]);
                }
        }
        __syncthreads();
    }
    #pragma unroll
    for (int i = 0; i < 4; i++) {
        #pragma unroll
        for (int j = 0; j < JT; j++) {
            int gr0 = row0 + wm*64 + i*16 + (lane >> 2);
            int gc  = col0 + wn*8*JT + j*8 + (lane & 3)*2;
            if (gc >= a.Nc) continue;
            #pragma unroll
            for (int h2 = 0; h2 < 2; h2++) {
                int gr = gr0 + h2*8;
                float v0 = acc[i][j][h2*2+0]*a.scale;
                float v1 = acc[i][j][h2*2+1]*a.scale;
                if (z.bias) {
                    if (a.bias_rows) { float bb=z.bias[gr]; v0+=bb; v1+=bb; }
                    else { v0+=z.bias[gc]; v1+=z.bias[gc+1]; }
                }
                if (z.res) {
                    v0 += z.res[(size_t)gr*a.ldo + gc];
                    v1 += z.res[(size_t)gr*a.ldo + gc + 1];
                }
                if (z.outF) {
                    z.outF[(size_t)gr*a.ldo + gc]   = v0;
                    z.outF[(size_t)gr*a.ldo + gc+1] = v1;
                }
                if (z.oh) {
                    if (z.cosv) {
                        int p = (gc & 63) >> 1;
                        float cv = z.cosv[gr*32+p], sv = z.sinv[gr*32+p];
                        float r0 = v0*cv - v1*sv;
                        float r1 = v1*cv + v0*sv;
                        v0 = r0; v1 = r1;
                    }
                    uint32_t hi, lo;
                    split2(v0, v1, hi, lo);
                    size_t o = (size_t)gr*a.ldh + gc;
                    *(uint32_t*)&z.oh[o] = hi;
                    *(uint32_t*)&z.ol[o] = lo;
                }
            }
        }
    }
}
#define SMEMB4 ((2*(2*AST+2*128*APAD))*2)
#define SMEMB2 ((2*(2*AST+2*64*APAD))*2)

// ---------- flash attention (R10/R13 config) ----------
#define KP 72
#define VP 136
#define FK_L (128*KP)
#define FV_H (2*128*KP)
#define FSTAGE (2*128*KP + 64*VP)
#define FSMEM_B (2*FSTAGE*2)
#define SC2 (0.125f*1.44269504088896f)

__global__ void __launch_bounds__(256)
flash_attn(const bf* __restrict__ qh_, const bf* __restrict__ ql_,
           const bf* __restrict__ kh_, const bf* __restrict__ kl_,
           const bf* __restrict__ vh_,
           bf* __restrict__ aoh_, bf* __restrict__ aol_) {
    extern __shared__ bf fsm[];
    int slice = blockIdx.y;
    int s = slice >> 2, h = slice & 3;
    const bf* qgh = qh_ + (size_t)s*SZ;
    const bf* qgl = ql_ + (size_t)s*SZ;
    const bf* kgh = kh_ + (size_t)s*SZ;
    const bf* kgl = kl_ + (size_t)s*SZ;
    const bf* vgh = vh_ + (size_t)s*SZ + (size_t)(h*64)*2048;
    bf* outh = aoh_ + (size_t)s*SZ;
    bf* outl = aol_ + (size_t)s*SZ;
    int hcol = h*64;
    int t = threadIdx.x, w = t>>5, lane = t&31;
    int qrow = blockIdx.x*128 + w*16 + (lane>>2);
    uint32_t smb = (uint32_t)__cvta_generic_to_shared(fsm);

    uint32_t Aqh[4][4], Aql[4][4];
    #pragma unroll
    for (int ks=0; ks<4; ks++) {
        int cb = hcol + ks*16 + (lane&3)*2;
        Aqh[ks][0] = *(const uint32_t*)&qgh[(size_t)qrow*256 + cb];
        Aqh[ks][1] = *(const uint32_t*)&qgh[(size_t)(qrow+8)*256 + cb];
        Aqh[ks][2] = *(const uint32_t*)&qgh[(size_t)qrow*256 + cb + 8];
        Aqh[ks][3] = *(const uint32_t*)&qgh[(size_t)(qrow+8)*256 + cb + 8];
        Aql[ks][0] = *(const uint32_t*)&qgl[(size_t)qrow*256 + cb];
        Aql[ks][1] = *(const uint32_t*)&qgl[(size_t)(qrow+8)*256 + cb];
        Aql[ks][2] = *(const uint32_t*)&qgl[(size_t)qrow*256 + cb + 8];
        Aql[ks][3] = *(const uint32_t*)&qgl[(size_t)(qrow+8)*256 + cb + 8];
    }

    auto issue = [&](int ch, int st) {
        uint32_t base = smb + (uint32_t)(st*FSTAGE*2);
        int key0 = ch*128;
        int kr = t>>1, kc = (t&1)*32;
        const bf* skh = kgh + (size_t)(key0+kr)*256 + hcol + kc;
        const bf* skl = kgl + (size_t)(key0+kr)*256 + hcol + kc;
        #pragma unroll
        for (int i=0;i<4;i++) {
            uint32_t d = base + (uint32_t)((kr*KP + kc + i*8)*2);
            CP16(d,           skh + i*8);
            CP16(d + FK_L*2,  skl + i*8);
        }
        int vr = t>>2, vc = (t&3)*32;
        const bf* svh = vgh + (size_t)vr*2048 + key0 + vc;
        #pragma unroll
        for (int i=0;i<4;i++) {
            uint32_t d = base + (uint32_t)((FV_H + vr*VP + vc + i*8)*2);
            CP16(d, svh + i*8);
        }
        asm volatile("cp.async.commit_group;");
    };

    float m_run[2] = {-1e30f, -1e30f};
    float s_run[2] = {0.f, 0.f};
    float oacc[8][4] = {};
    int l15 = lane & 15, lhi = (lane >> 4)*8;

    issue(0, 0);
    for (int ch = 0; ch < 16; ch++) {
        int st = ch & 1;
        if (ch + 1 < 16) { issue(ch+1, st^1); asm volatile("cp.async.wait_group 1;"); }
        else             { asm volatile("cp.async.wait_group 0;"); }
        __syncthreads();
        uint32_t bKh = smb + (uint32_t)(st*FSTAGE*2);
        uint32_t bKl = bKh + FK_L*2;
        uint32_t bVh = bKh + FV_H*2;

        float sacc[16][4] = {};
        #pragma unroll
        for (int ks = 0; ks < 4; ks++) {
            #pragma unroll
            for (int j = 0; j < 16; j += 2) {
                uint32_t koff = (uint32_t)(((j*8 + l15)*KP + ks*16 + lhi)*2);
                uint32_t Bh[2][2], Bl[2][2];
                ldsm4(Bh[0][0],Bh[1][0],Bh[0][1],Bh[1][1], bKh + koff);
                ldsm4(Bl[0][0],Bl[1][0],Bl[0][1],Bl[1][1], bKl + koff);
                mma16816(sacc[j],   Aqh[ks], Bh[0]);
                mma16816(sacc[j],   Aqh[ks], Bl[0]);
                mma16816(sacc[j],   Aql[ks], Bh[0]);
                mma16816(sacc[j+1], Aqh[ks], Bh[1]);
                mma16816(sacc[j+1], Aqh[ks], Bl[1]);
                mma16816(sacc[j+1], Aql[ks], Bh[1]);
            }
        }
        float mx0 = -1e30f, mx1 = -1e30f;
        #pragma unroll
        for (int j = 0; j < 16; j++) {
            sacc[j][0]*=SC2; sacc[j][1]*=SC2; sacc[j][2]*=SC2; sacc[j][3]*=SC2;
            mx0 = fmaxf(mx0, fmaxf(sacc[j][0], sacc[j][1]));
            mx1 = fmaxf(mx1, fmaxf(sacc[j][2], sacc[j][3]));
        }
        mx0 = fmaxf(mx0, __shfl_xor_sync(0xffffffffu, mx0, 1));
        mx0 = fmaxf(mx0, __shfl_xor_sync(0xffffffffu, mx0, 2));
        mx1 = fmaxf(mx1, __shfl_xor_sync(0xffffffffu, mx1, 1));
        mx1 = fmaxf(mx1, __shfl_xor_sync(0xffffffffu, mx1, 2));
        float nm0 = fmaxf(m_run[0], mx0), nm1 = fmaxf(m_run[1], mx1);
        float al0 = exp2f(m_run[0]-nm0), al1 = exp2f(m_run[1]-nm1);
        float cs0 = 0.f, cs1 = 0.f;
        #pragma unroll
        for (int j = 0; j < 16; j++) {
            float p0=exp2f(sacc[j][0]-nm0), p1=exp2f(sacc[j][1]-nm0);
            float p2=exp2f(sacc[j][2]-nm1), p3=exp2f(sacc[j][3]-nm1);
            sacc[j][0]=p0; sacc[j][1]=p1; sacc[j][2]=p2; sacc[j][3]=p3;
            cs0 += p0+p1; cs1 += p2+p3;
        }
        cs0 += __shfl_xor_sync(0xffffffffu, cs0, 1);
        cs0 += __shfl_xor_sync(0xffffffffu, cs0, 2);
        cs1 += __shfl_xor_sync(0xffffffffu, cs1, 1);
        cs1 += __shfl_xor_sync(0xffffffffu, cs1, 2);
        s_run[0] = s_run[0]*al0 + cs0;
        s_run[1] = s_run[1]*al1 + cs1;
        m_run[0] = nm0; m_run[1] = nm1;
        #pragma unroll
        for (int j2 = 0; j2 < 8; j2++) {
            oacc[j2][0]*=al0; oacc[j2][1]*=al0; oacc[j2][2]*=al1; oacc[j2][3]*=al1;
        }
        #pragma unroll
        for (int kk = 0; kk < 8; kk++) {
            uint32_t Pah[4];
            Pah[0] = pkbf(sacc[2*kk  ][0], sacc[2*kk  ][1]);
            Pah[1] = pkbf(sacc[2*kk  ][2], sacc[2*kk  ][3]);
            Pah[2] = pkbf(sacc[2*kk+1][0], sacc[2*kk+1][1]);
            Pah[3] = pkbf(sacc[2*kk+1][2], sacc[2*kk+1][3]);
            #pragma unroll
            for (int j2 = 0; j2 < 8; j2 += 2) {
                uint32_t voff = (uint32_t)(((j2*8 + l15)*VP + kk*16 + lhi)*2);
                uint32_t Bh[2][2];
                ldsm4(Bh[0][0],Bh[1][0],Bh[0][1],Bh[1][1], bVh + voff);
                mma16816(oacc[j2],   Pah, Bh[0]);
                mma16816(oacc[j2+1], Pah, Bh[1]);
            }
        }
        __syncthreads();
    }
    float inv0 = 1.0f/s_run[0], inv1 = 1.0f/s_run[1];
    #pragma unroll
    for (int j2 = 0; j2 < 8; j2++) {
        int col = hcol + j2*8 + (lane&3)*2;
        uint32_t hi, lo;
        split2(oacc[j2][0]*inv0, oacc[j2][1]*inv0, hi, lo);
        *(uint32_t*)&outh[(size_t)qrow*256 + col] = hi;
        *(uint32_t*)&outl[(size_t)qrow*256 + col] = lo;
        split2(oacc[j2][2]*inv1, oacc[j2][3]*inv1, hi, lo);
        *(uint32_t*)&outh[(size_t)(qrow+8)*256 + col] = hi;
        *(uint32_t*)&outl[(size_t)(qrow+8)*256 + col] = lo;
    }
}

// ---------- fused one-time weight conversion ----------
#define WC_P  ((size_t)30*65536)
#define WC_M  ((size_t)10*65536)
#define WC_1  ((size_t)10*262144)
#define WC_2  ((size_t)10*131072)
#define WC_F  ((size_t)65536)
#define WC_TOT (WC_P+WC_M+WC_1+WC_2+WC_F)
__global__ void wconv_all(const float* __restrict__ pw, const float* __restrict__ mw,
                          const float* __restrict__ w1, const float* __restrict__ w2,
                          const float* __restrict__ fw,
                          bf* wqh, bf* wql, bf* wmh, bf* wml,
                          bf* w1h, bf* w1l, bf* w2h, bf* w2l, bf* fph, bf* fpl) {
    size_t idx = (size_t)blockIdx.x*256 + threadIdx.x;
    if (idx >= WC_TOT) return;
    bf *oh, *ol; size_t li;
    float v;
    if (idx < WC_P) {
        li = idx;
        int op=(li>>8)&255; int o=(op&63)*4+(op>>6);
        v = pw[(li & ~(size_t)0xFF00) | ((size_t)o<<8)];
        oh = wqh; ol = wql;
    } else if (idx < WC_P+WC_M) {
        li = idx - WC_P;
        int cp=li&255; int c=(cp&63)*4+(cp>>6);
        v = mw[(li & ~(size_t)0xFF) | (size_t)c];
        oh = wmh; ol = wml;
    } else if (idx < WC_P+WC_M+WC_1) {
        li = idx - WC_P - WC_M;
        v = w1[li]; oh = w1h; ol = w1l;
    } else if (idx < WC_P+WC_M+WC_1+WC_2) {
        li = idx - WC_P - WC_M - WC_1;
        v = w2[li]; oh = w2h; ol = w2l;
    } else {
        li = idx - WC_P - WC_M - WC_1 - WC_2;
        v = fw[li]; oh = fph; ol = fpl;
    }
    bf h = __float2bfloat16(v);
    oh[li]=h; ol[li]=__float2bfloat16(v-__bfloat162float(h));
}
__global__ void bias_perm(const float* __restrict__ pb, float* __restrict__ out) {
    int idx = blockIdx.x*256 + threadIdx.x;
    int op = idx & 255;
    out[idx] = pb[(idx & ~255) | ((op&63)*4 + (op>>6))];
}
struct TArgs { const float* in[2]; float* xF[2]; bf *yh[2], *yl[2]; };
__global__ void transpose_split(TArgs a) {
    __shared__ float tl[32][33];
    int zz = blockIdx.z, n0 = blockIdx.x*32, c0 = blockIdx.y*32;
    int tx = threadIdx.x&31, ty = threadIdx.x>>5;
    const float* in = a.in[zz];
    #pragma unroll
    for (int r=0;r<4;r++) tl[ty+r*8][tx] = in[(size_t)(c0+ty+r*8)*NN + n0+tx];
    __syncthreads();
    #pragma unroll
    for (int r=0;r<4;r++) {
        int n=n0+ty+r*8, c=c0+tx;
        float v = tl[tx][ty+r*8];
        a.xF[zz][(size_t)n*256+c]=v;
        bf h=__float2bfloat16(v);
        a.yh[zz][(size_t)n*512+c]=h;
        a.yl[zz][(size_t)n*512+c]=__float2bfloat16(v-__bfloat162float(h));
    }
}
__global__ void posenc_kernel(const float* __restrict__ kpts, const float* __restrict__ Wr,
                              float* __restrict__ cosv, float* __restrict__ sinv) {
    int idx = blockIdx.x*256 + threadIdx.x;
    if (idx >= NN*32) return;
    int p = idx & 31, n = idx >> 5;
    float kx = (kpts[2*n+0]-512.0f)*(1.0f/716.8f);
    float ky = (kpts[2*n+1]-384.0f)*(1.0f/716.8f);
    float pr = kx*Wr[2*p+0] + ky*Wr[2*p+1];
    cosv[idx] = cosf(pr); sinv[idx] = sinf(pr);
}
// ---------- batchnorm: full-grid two-pass ----------
__global__ void __launch_bounds__(256)
bn_stats(const float* __restrict__ hf, float* __restrict__ pS, float* __restrict__ pQ) {
    int z = blockIdx.z;
    size_t base = (size_t)z * HSZ;
    int l = threadIdx.x & 63, rr = threadIdx.x >> 6;
    int c = blockIdx.x*64 + l;
    int r0 = blockIdx.y*128;
    float su=0.f, sq=0.f;
    for (int n = r0+rr; n < r0+128; n += 4) {
        float x = hf[base + (size_t)n*512 + c];
        su += x; sq += x*x;
    }
    __shared__ float sS[4][64], sQ[4][64];
    sS[rr][l]=su; sQ[rr][l]=sq;
    __syncthreads();
    if (rr==0) {
        float S=0.f, Q=0.f;
        #pragma unroll
        for (int i=0;i<4;i++){ S+=sS[i][l]; Q+=sQ[i][l]; }
        int o = (z*16 + blockIdx.y)*512 + c;
        pS[o]=S; pQ[o]=Q;
    }
}
__global__ void __launch_bounds__(256)
bn_apply(const float* __restrict__ hf, const float* __restrict__ pS, const float* __restrict__ pQ,
         const float* __restrict__ g, const float* __restrict__ b,
         bf* __restrict__ oh, bf* __restrict__ ol) {
    int z = blockIdx.z;
    size_t base = (size_t)z * HSZ;
    __shared__ float sc[64], sh[64];
    int l = threadIdx.x & 63;
    if (threadIdx.x < 64) {
        int c = blockIdx.x*64 + threadIdx.x;
        float S=0.f, Q=0.f;
        #pragma unroll
        for (int k=0;k<16;k++){ S+=pS[(z*16+k)*512+c]; Q+=pQ[(z*16+k)*512+c]; }
        float mean=S*(1.0f/NN), var=Q*(1.0f/NN)-mean*mean;
        float s1=g[c]*rsqrtf(var+1e-5f);
        sc[threadIdx.x]=s1; sh[threadIdx.x]=b[c]-mean*s1;
    }
    __syncthreads();
    int c = blockIdx.x*64 + l;
    int rr = threadIdx.x >> 6, r0 = blockIdx.y*128;
    float s1=sc[l], s2=sh[l];
    for (int n = r0+rr; n < r0+128; n += 4) {
        float v=fmaxf(hf[base+(size_t)n*512+c]*s1+s2, 0.0f);
        bf h=__float2bfloat16(v);
        oh[base+(size_t)n*512+c]=h;
        ol[base+(size_t)n*512+c]=__float2bfloat16(v-__bfloat162float(h));
    }
}
// ---------- Sinkhorn ----------
__global__ void bins_zero_kernel(float* __restrict__ C, const float* __restrict__ a,
                                 float* __restrict__ vv) {
    int i = blockIdx.x*256 + threadIdx.x;
    if (i >= NP1) return;
    float v = a[0];
    C[(size_t)i*NP1 + NN] = v;
    C[(size_t)NN*NP1 + i] = v;
    vv[i] = 0.0f;
}
// single-pass online LSE per row
__global__ void __launch_bounds__(256)
u_update_kernel(const float* __restrict__ C, const float* __restrict__ vv, float* __restrict__ u) {
    __shared__ float smM[8], smS[8];
    int i = blockIdx.x;
    const float* row = C + (size_t)i*NP1;
    int t = threadIdx.x;
    float m = -1e30f, s = 0.f;
    for (int j=t; j<NP1; j+=256) {
        float x = row[j] + vv[j];
        if (x > m) { s = s*__expf(m-x) + 1.f; m = x; }
        else       { s += __expf(x-m); }
    }
    #pragma unroll
    for (int o=16;o>0;o>>=1) {
        float m2 = __shfl_xor_sync(0xffffffffu, m, o);
        float s2 = __shfl_xor_sync(0xffffffffu, s, o);
        float M = fmaxf(m, m2);
        s = s*__expf(m-M) + s2*__expf(m2-M);
        m = M;
    }
    if ((t&31)==0) { smM[t>>5]=m; smS[t>>5]=s; }
    __syncthreads();
    if (t==0) {
        float M = smM[0];
        #pragma unroll
        for (int w2=1; w2<8; w2++) M = fmaxf(M, smM[w2]);
        float S = 0.f;
        #pragma unroll
        for (int w2=0; w2<8; w2++) S += smS[w2]*__expf(smM[w2]-M);
        u[i] = ((i<NN)?NORMC:(LOGN+NORMC)) - (M + logf(S));
    }
}
// fused v: partials + last-block combine
__global__ void v_fused_kernel(const float* __restrict__ C, const float* __restrict__ u,
                               float* __restrict__ pm, float* __restrict__ ps,
                               float* __restrict__ vv, int* __restrict__ cnt) {
    __shared__ int lastFlag;
    int j = blockIdx.x*256 + threadIdx.x;
    int rc = blockIdx.y, i0 = rc*129, i1 = min(i0+129, NP1);
    if (j < NP1) {
        float m=-1e30f, s=0.f;
        for (int i=i0; i<i1; i++) {
            float x = C[(size_t)i*NP1+j] + u[i];
            if (x>m) { s=s*__expf(m-x)+1.f; m=x; } else s+=__expf(x-m);
        }
        pm[rc*NP1+j]=m; ps[rc*NP1+j]=s;
    }
    __threadfence();
    __syncthreads();
    if (threadIdx.x == 0) {
        int prev = atomicAdd(&cnt[blockIdx.x], 1);
        lastFlag = (prev == 15);
    }
    __syncthreads();
    if (lastFlag) {
        if (j < NP1) {
            float M=-1e30f;
            #pragma unroll
            for (int r2=0;r2<16;r2++) M=fmaxf(M, pm[r2*NP1+j]);
            float S=0.f;
            #pragma unroll
            for (int r2=0;r2<16;r2++) S+=ps[r2*NP1+j]*__expf(pm[r2*NP1+j]-M);
            vv[j] = ((j<NN)?NORMC:(LOGN+NORMC)) - (M + logf(S));
        }
        if (threadIdx.x == 0) cnt[blockIdx.x] = 0;   // reset for next iteration / replay
    }
}
__global__ void final_add_kernel(float* __restrict__ C, const float* __restrict__ u,
                                 const float* __restrict__ vv) {
    int j = blockIdx.x*256 + threadIdx.x;
    int i = blockIdx.y;
    if (j >= NP1) return;
    C[(size_t)i*NP1 + j] += u[i] + vv[j] + LOG4096;
}

// ---------- host ----------
#define GSA(p,s) cudaGetSymbolAddress((void**)&(p), s)
extern "C" void kernel_launch(void* const* d_in, const int* in_sizes, int n_in,
                              void* d_out, int out_size) {
    (void)in_sizes; (void)n_in; (void)out_size;
    const float *desc0=(const float*)d_in[0], *desc1=(const float*)d_in[1];
    const float *kpts0=(const float*)d_in[2], *kpts1=(const float*)d_in[3];
    const float *Wr=(const float*)d_in[4], *proj_w=(const float*)d_in[5];
    const float *proj_b=(const float*)d_in[6];
    const float *merge_w=(const float*)d_in[7], *merge_b=(const float*)d_in[8];
    const float *mlp_w1=(const float*)d_in[9], *mlp_b1=(const float*)d_in[10];
    const float *bn_g=(const float*)d_in[11], *bn_b=(const float*)d_in[12];
    const float *mlp_w2=(const float*)d_in[13], *mlp_b2=(const float*)d_in[14];
    const float *fp_w=(const float*)d_in[15], *fp_b=(const float*)d_in[16];
    const float *binsc=(const float*)d_in[17];
    float* C = (float*)d_out;

    cudaFuncSetAttribute(mma_gemm<4>, cudaFuncAttributeMaxDynamicSharedMemorySize, SMEMB4);
    cudaFuncSetAttribute(mma_gemm<2>, cudaFuncAttributeMaxDynamicSharedMemorySize, SMEMB2);
    cudaFuncSetAttribute(flash_attn, cudaFuncAttributeMaxDynamicSharedMemorySize, FSMEM_B);

    float *xF,*hf,*pbp,*cs,*pu,*pvv,*ppm,*pps,*bnS,*bnQ;
    int *pcnt;
    bf *yh,*yl,*qh,*ql,*kh,*kl,*vh,*vl,*aoh,*aol,*hh,*hl;
    bf *wqh,*wql,*wmh,*wml,*w1h,*w1l,*w2h,*w2l,*fph,*fpl;
    GSA(xF,g_xF); GSA(hf,g_hf);
    GSA(yh,g_yh); GSA(yl,g_yl); GSA(qh,g_qh); GSA(ql,g_ql);
    GSA(kh,g_kh); GSA(kl,g_kl); GSA(vh,g_vh); GSA(vl,g_vl);
    GSA(aoh,g_aoh); GSA(aol,g_aol); GSA(hh,g_hh); GSA(hl,g_hl);
    GSA(wqh,g_wqh); GSA(wql,g_wql); GSA(wmh,g_wmh); GSA(wml,g_wml);
    GSA(w1h,g_w1h); GSA(w1l,g_w1l); GSA(w2h,g_w2h); GSA(w2l,g_w2l);
    GSA(fph,g_fph); GSA(fpl,g_fpl); GSA(pbp,g_pbp); GSA(cs,g_cs);
    GSA(bnS,g_bnS); GSA(bnQ,g_bnQ);
    GSA(pu,g_u); GSA(pvv,g_vv); GSA(ppm,g_pm); GSA(pps,g_ps);
    GSA(pcnt,g_cnt);
    float *c0=cs, *s0=cs+NN*32, *c1=cs+2*NN*32, *s1=cs+3*NN*32;

    wconv_all<<<(unsigned)((WC_TOT+255)/256),256>>>(proj_w, merge_w, mlp_w1, mlp_w2, fp_w,
                                                    wqh, wql, wmh, wml, w1h, w1l, w2h, w2l, fph, fpl);
    bias_perm<<<30,256>>>(proj_b, pbp);
    posenc_kernel<<<NN*32/256,256>>>(kpts0, Wr, c0, s0);
    posenc_kernel<<<NN*32/256,256>>>(kpts1, Wr, c1, s1);
    TArgs ta;
    ta.in[0]=desc0; ta.in[1]=desc1;
    for (int s=0;s<2;s++){ ta.xF[s]=xF+s*SZ; ta.yh[s]=yh+s*HSZ; ta.yl[s]=yl+s*HSZ; }
    transpose_split<<<dim3(64,8,2),256>>>(ta);

    for (int l=0; l<10; l++) {
        int even = !(l&1);
        int src[2] = { even?0:1, even?1:0 };
        const float* mb  = merge_b + l*256;
        const float* b1  = mlp_b1 + l*512;
        const float* b2  = mlp_b2 + l*256;
        const float* csv[2] = { c0, c1 };
        const float* snv[2] = { s0, s1 };

        // q,k projections with fused RoPE+split — JT=4
        MArgs mq = {};
        mq.lda=512; mq.ldb=256; mq.ldo=256; mq.ldh=256; mq.K=256; mq.Nc=256; mq.scale=1.f;
        for (int s=0;s<2;s++) {
            MZ* zq=&mq.z[s*2], *zk=&mq.z[s*2+1];
            zq->Ah=yh+s*HSZ; zq->Al=yl+s*HSZ;
            zq->Bh=wqh+(size_t)(l*3)*65536; zq->Bl=wql+(size_t)(l*3)*65536;
            zq->bias=pbp+(l*3)*256; zq->oh=qh+s*SZ; zq->ol=ql+s*SZ;
            zk->Ah=yh+src[s]*HSZ; zk->Al=yl+src[s]*HSZ;
            zk->Bh=wqh+(size_t)(l*3+1)*65536; zk->Bl=wql+(size_t)(l*3+1)*65536;
            zk->bias=pbp+(l*3+1)*256; zk->oh=kh+s*SZ; zk->ol=kl+s*SZ;
            if (even) {
                zq->cosv=csv[s]; zq->sinv=snv[s];
                zk->cosv=csv[s]; zk->sinv=snv[s];
            }
        }
        mma_gemm<4><<<dim3(16,2,4),256,SMEMB4>>>(mq);

        // v projection (transposed out) — JT=2
        MArgs mv = {};
        mv.lda=256; mv.ldb=512; mv.ldo=2048; mv.ldh=2048; mv.K=256; mv.Nc=2048;
        mv.scale=1.f; mv.bias_rows=1;
        for (int s=0;s<2;s++) {
            MZ* zv=&mv.z[s];
            zv->Ah=wqh+(size_t)(l*3+2)*65536; zv->Al=wql+(size_t)(l*3+2)*65536;
            zv->Bh=yh+src[s]*HSZ; zv->Bl=yl+src[s]*HSZ;
            zv->bias=pbp+(l*3+2)*256; zv->oh=vh+s*SZ; zv->ol=vl+s*SZ;
        }
        mma_gemm<2><<<dim3(2,32,2),256,SMEMB2>>>(mv);

        // fused attention
        flash_attn<<<dim3(16,8),256,FSMEM_B>>>(qh,ql,kh,kl,vh,aoh,aol);

        // merge -> y cols 256:511 — JT=2
        MArgs mm = {};
        mm.lda=256; mm.ldb=256; mm.ldh=512; mm.K=256; mm.Nc=256; mm.scale=1.f;
        for (int s=0;s<2;s++) {
            MZ* zz=&mm.z[s];
            zz->Ah=aoh+s*SZ; zz->Al=aol+s*SZ;
            zz->Bh=wmh+(size_t)l*65536; zz->Bl=wml+(size_t)l*65536;
            zz->bias=mb; zz->oh=yh+s*HSZ+256; zz->ol=yl+s*HSZ+256;
        }
        mma_gemm<2><<<dim3(16,4,2),256,SMEMB2>>>(mm);

        // mlp1 -> h fp32 — JT=4
        MArgs m1 = {};
        m1.lda=512; m1.ldb=512; m1.ldo=512; m1.K=512; m1.Nc=512; m1.scale=1.f;
        for (int s=0;s<2;s++) {
            MZ* zz=&m1.z[s];
            zz->Ah=yh+s*HSZ; zz->Al=yl+s*HSZ;
            zz->Bh=w1h+(size_t)l*262144; zz->Bl=w1l+(size_t)l*262144;
            zz->bias=b1; zz->outF=hf+s*HSZ;
        }
        mma_gemm<4><<<dim3(16,4,2),256,SMEMB4>>>(m1);
        bn_stats<<<dim3(8,16,2),256>>>(hf, bnS, bnQ);
        bn_apply<<<dim3(8,16,2),256>>>(hf, bnS, bnQ, bn_g+l*512, bn_b+l*512, hh, hl);

        // mlp2 + residual — JT=2
        MArgs m2 = {};
        m2.lda=512; m2.ldb=512; m2.ldo=256; m2.ldh=512; m2.K=512; m2.Nc=256; m2.scale=1.f;
        for (int s=0;s<2;s++) {
            MZ* zz=&m2.z[s];
            zz->Ah=hh+s*HSZ; zz->Al=hl+s*HSZ;
            zz->Bh=w2h+(size_t)l*131072; zz->Bl=w2l+(size_t)l*131072;
            zz->bias=b2; zz->res=xF+s*SZ; zz->outF=xF+s*SZ;
            zz->oh=yh+s*HSZ; zz->ol=yl+s*HSZ;
        }
        mma_gemm<2><<<dim3(16,4,2),256,SMEMB2>>>(m2);
    }

    // final projection — JT=2
    MArgs mf = {};
    mf.lda=512; mf.ldb=256; mf.ldh=256; mf.K=256; mf.Nc=256; mf.scale=1.f;
    for (int s=0;s<2;s++) {
        MZ* zz=&mf.z[s];
        zz->Ah=yh+s*HSZ; zz->Al=yl+s*HSZ;
        zz->Bh=fph; zz->Bl=fpl;
        zz->bias=fp_b; zz->oh=qh+s*SZ; zz->ol=ql+s*SZ;
    }
    mma_gemm<2><<<dim3(16,4,2),256,SMEMB2>>>(mf);

    // final match scores into C (ld 2049) — JT=4
    MArgs mc = {};
    mc.lda=256; mc.ldb=256; mc.ldo=NP1; mc.K=256; mc.Nc=2048; mc.scale=0.0625f;
    mc.z[0].Ah=qh; mc.z[0].Al=ql; mc.z[0].Bh=qh+SZ; mc.z[0].Bl=ql+SZ;
    mc.z[0].outF=C;
    mma_gemm<4><<<dim3(16,16,1),256,SMEMB4>>>(mc);
    bins_zero_kernel<<<(NP1+255)/256,256>>>(C, binsc, pvv);

    for (int t=0; t<20; t++) {
        u_update_kernel<<<NP1,256>>>(C, pvv, pu);
        v_fused_kernel<<<dim3((NP1+255)/256,16),256>>>(C, pu, ppm, pps, pvv, pcnt);
    }
    final_add_kernel<<<dim3((NP1+255)/256, NP1),256>>>(C, pu, pvv);
}

// round 15
// speedup vs baseline: 1.0464x; 1.0464x over previous
#include <cuda_runtime.h>
#include <cuda_bf16.h>
#include <math.h>
#include <stdint.h>

#define NN 2048
#define DM 256
#define NP1 2049
#define NORMC (-8.317766166719343f)
#define LOGN (7.624618986159398f)
#define LOG4096 (8.317766166719343f)
#define SZ ((size_t)NN*DM)
#define HSZ ((size_t)NN*512)
typedef __nv_bfloat16 bf;

// ---------- static scratch ----------
__device__ float g_xF[2*SZ], g_hf[2*HSZ];
__device__ bf g_yh[2*HSZ], g_yl[2*HSZ];
__device__ bf g_qh[2*SZ], g_ql[2*SZ], g_kh[2*SZ], g_kl[2*SZ];
__device__ bf g_vh[2*SZ], g_vl[2*SZ], g_aoh[2*SZ], g_aol[2*SZ];
__device__ bf g_hh[2*HSZ], g_hl[2*HSZ];
__device__ bf g_wqh[30*65536], g_wql[30*65536], g_wmh[10*65536], g_wml[10*65536];
__device__ bf g_w1h[10*262144], g_w1l[10*262144], g_w2h[10*131072], g_w2l[10*131072];
__device__ bf g_fph[65536], g_fpl[65536];
__device__ float g_pbp[30*256];
__device__ float g_cs[4*NN*32];
__device__ float g_bnS[2*16*512], g_bnQ[2*16*512];
__device__ float g_u[NP1], g_vv[NP1], g_pm[32*NP1], g_ps[32*NP1];

// ---------- HMMA m16n8k16 bf16 + ldmatrix ----------
__device__ __forceinline__ void mma16816(float* c, const uint32_t* a, const uint32_t* b) {
    asm volatile("mma.sync.aligned.m16n8k16.row.col.f32.bf16.bf16.f32 "
        "{%0,%1,%2,%3}, {%4,%5,%6,%7}, {%8,%9}, {%0,%1,%2,%3};"
        : "+f"(c[0]), "+f"(c[1]), "+f"(c[2]), "+f"(c[3])
        : "r"(a[0]), "r"(a[1]), "r"(a[2]), "r"(a[3]), "r"(b[0]), "r"(b[1]));
}
__device__ __forceinline__ void ldsm4(uint32_t& r0, uint32_t& r1, uint32_t& r2, uint32_t& r3,
                                      uint32_t addr) {
    asm volatile("ldmatrix.sync.aligned.m8n8.x4.shared.b16 {%0,%1,%2,%3}, [%4];"
        : "=r"(r0), "=r"(r1), "=r"(r2), "=r"(r3) : "r"(addr));
}
#define CP16(dst, src) asm volatile("cp.async.ca.shared.global [%0], [%1], 16;" :: "r"(dst), "l"(src))

__device__ __forceinline__ uint32_t pkbf(float x, float y) {
    __nv_bfloat162 t = __floats2bfloat162_rn(x, y);
    return *(uint32_t*)&t;
}
__device__ __forceinline__ void split2(float x, float y, uint32_t& hi, uint32_t& lo) {
    bf hx = __float2bfloat16(x), hy = __float2bfloat16(y);
    __nv_bfloat162 hp; hp.x = hx; hp.y = hy;
    hi = *(uint32_t*)&hp;
    lo = pkbf(x - __bfloat162float(hx), y - __bfloat162float(hy));
}

// ---------- generic split-bf16 HMMA GEMM (2-stage cp.async) ----------
struct MZ { const bf *Ah,*Al,*Bh,*Bl; const float *bias,*res; float *outF; bf *oh,*ol;
            const float *cosv,*sinv; };
struct MArgs { MZ z[8]; int lda,ldb,ldo,ldh,K,Nc,bias_rows; float scale; };

#define APAD 72
#define AST (128*APAD)

template<int JT>
__global__ void __launch_bounds__(256) mma_gemm(MArgs a) {
    constexpr int CTAC = 32*JT;
    constexpr int BST = CTAC*APAD;
    constexpr int STAGE = 2*AST + 2*BST;
    extern __shared__ bf smem[];
    MZ z = a.z[blockIdx.z];
    int t = threadIdx.x, w = t>>5, lane = t&31;
    int wm = w & 1, wn = w >> 1;
    int row0 = blockIdx.x*128, col0 = blockIdx.y*CTAC;
    uint32_t smb = (uint32_t)__cvta_generic_to_shared(smem);
    int lr = t >> 3, lc = (t & 7) * 8;
    int nch = a.K >> 6;

    auto issue = [&](int ch, int st) {
        uint32_t base = smb + (uint32_t)(st*STAGE*2);
        const bf* Agh = z.Ah + (size_t)(row0+lr)*a.lda + ch*64 + lc;
        const bf* Agl = z.Al + (size_t)(row0+lr)*a.lda + ch*64 + lc;
        #pragma unroll
        for (int it=0; it<4; it++) {
            uint32_t d = base + (uint32_t)(((lr+it*32)*APAD + lc)*2);
            CP16(d,           Agh + (size_t)it*32*a.lda);
            CP16(d + AST*2,   Agl + (size_t)it*32*a.lda);
        }
        uint32_t bb = base + 2*AST*2;
        #pragma unroll
        for (int it=0; it<JT; it++) {
            int r = lr + it*32;
            if (col0 + r < a.Nc) {
                uint32_t d = bb + (uint32_t)((r*APAD + lc)*2);
                CP16(d,         z.Bh + (size_t)(col0+r)*a.ldb + ch*64 + lc);
                CP16(d + BST*2, z.Bl + (size_t)(col0+r)*a.ldb + ch*64 + lc);
            }
        }
        asm volatile("cp.async.commit_group;");
    };

    float acc[4][JT][4] = {};
    issue(0, 0);
    for (int ch = 0; ch < nch; ch++) {
        int st = ch & 1;
        if (ch + 1 < nch) {
            issue(ch+1, st^1);
            asm volatile("cp.async.wait_group 1;");
        } else {
            asm volatile("cp.async.wait_group 0;");
        }
        __syncthreads();
        uint32_t bAh = smb + (uint32_t)(st*STAGE*2);
        uint32_t bAl = bAh + AST*2;
        uint32_t bBh = bAh + 2*AST*2;
        uint32_t bBl = bBh + BST*2;
        int l15 = lane & 15, lhi = (lane >> 4)*8;
        #pragma unroll
        for (int ks = 0; ks < 4; ks++) {
            uint32_t Afh[4][4], Afl[4][4], Bfh[JT][2], Bfl[JT][2];
            uint32_t aoff = (uint32_t)(((wm*64 + l15)*APAD + ks*16 + lhi)*2);
            #pragma unroll
            for (int i = 0; i < 4; i++) {
                ldsm4(Afh[i][0],Afh[i][1],Afh[i][2],Afh[i][3], bAh + aoff + (uint32_t)(i*16*APAD*2));
                ldsm4(Afl[i][0],Afl[i][1],Afl[i][2],Afl[i][3], bAl + aoff + (uint32_t)(i*16*APAD*2));
            }
            #pragma unroll
            for (int j = 0; j < JT; j += 2) {
                uint32_t boff = (uint32_t)(((wn*8*JT + j*8 + l15)*APAD + ks*16 + lhi)*2);
                ldsm4(Bfh[j][0],Bfh[j+1][0],Bfh[j][1],Bfh[j+1][1], bBh + boff);
                ldsm4(Bfl[j][0],Bfl[j+1][0],Bfl[j][1],Bfl[j+1][1], bBl + boff);
            }
            #pragma unroll
            for (int i = 0; i < 4; i++)
                #pragma unroll
                for (int j = 0; j < JT; j++) {
                    mma16816(acc[i][j], Afh[i], Bfh[j]);
                    mma16816(acc[i][j], Afh[i], Bfl[j]);
                    mma16816(acc[i][j], Afl[i], Bfh[j]);
                }
        }
        __syncthreads();
    }
    #pragma unroll
    for (int i = 0; i < 4; i++) {
        #pragma unroll
        for (int j = 0; j < JT; j++) {
            int gr0 = row0 + wm*64 + i*16 + (lane >> 2);
            int gc  = col0 + wn*8*JT + j*8 + (lane & 3)*2;
            if (gc >= a.Nc) continue;
            #pragma unroll
            for (int h2 = 0; h2 < 2; h2++) {
                int gr = gr0 + h2*8;
                float v0 = acc[i][j][h2*2+0]*a.scale;
                float v1 = acc[i][j][h2*2+1]*a.scale;
                if (z.bias) {
                    if (a.bias_rows) { float bb=z.bias[gr]; v0+=bb; v1+=bb; }
                    else { v0+=z.bias[gc]; v1+=z.bias[gc+1]; }
                }
                if (z.res) {
                    v0 += z.res[(size_t)gr*a.ldo + gc];
                    v1 += z.res[(size_t)gr*a.ldo + gc + 1];
                }
                if (z.outF) {
                    z.outF[(size_t)gr*a.ldo + gc]   = v0;
                    z.outF[(size_t)gr*a.ldo + gc+1] = v1;
                }
                if (z.oh) {
                    if (z.cosv) {
                        int p = (gc & 63) >> 1;
                        float cv = z.cosv[gr*32+p], sv = z.sinv[gr*32+p];
                        float r0 = v0*cv - v1*sv;
                        float r1 = v1*cv + v0*sv;
                        v0 = r0; v1 = r1;
                    }
                    uint32_t hi, lo;
                    split2(v0, v1, hi, lo);
                    size_t o = (size_t)gr*a.ldh + gc;
                    *(uint32_t*)&z.oh[o] = hi;
                    *(uint32_t*)&z.ol[o] = lo;
                }
            }
        }
    }
}
#define SMEMB4 ((2*(2*AST+2*128*APAD))*2)
#define SMEMB2 ((2*(2*AST+2*64*APAD))*2)

// ---------- flash attention (R10/R13 config) ----------
#define KP 72
#define VP 136
#define FK_L (128*KP)
#define FV_H (2*128*KP)
#define FSTAGE (2*128*KP + 64*VP)
#define FSMEM_B (2*FSTAGE*2)
#define SC2 (0.125f*1.44269504088896f)

__global__ void __launch_bounds__(256)
flash_attn(const bf* __restrict__ qh_, const bf* __restrict__ ql_,
           const bf* __restrict__ kh_, const bf* __restrict__ kl_,
           const bf* __restrict__ vh_,
           bf* __restrict__ aoh_, bf* __restrict__ aol_) {
    extern __shared__ bf fsm[];
    int slice = blockIdx.y;
    int s = slice >> 2, h = slice & 3;
    const bf* qgh = qh_ + (size_t)s*SZ;
    const bf* qgl = ql_ + (size_t)s*SZ;
    const bf* kgh = kh_ + (size_t)s*SZ;
    const bf* kgl = kl_ + (size_t)s*SZ;
    const bf* vgh = vh_ + (size_t)s*SZ + (size_t)(h*64)*2048;
    bf* outh = aoh_ + (size_t)s*SZ;
    bf* outl = aol_ + (size_t)s*SZ;
    int hcol = h*64;
    int t = threadIdx.x, w = t>>5, lane = t&31;
    int qrow = blockIdx.x*128 + w*16 + (lane>>2);
    uint32_t smb = (uint32_t)__cvta_generic_to_shared(fsm);

    uint32_t Aqh[4][4], Aql[4][4];
    #pragma unroll
    for (int ks=0; ks<4; ks++) {
        int cb = hcol + ks*16 + (lane&3)*2;
        Aqh[ks][0] = *(const uint32_t*)&qgh[(size_t)qrow*256 + cb];
        Aqh[ks][1] = *(const uint32_t*)&qgh[(size_t)(qrow+8)*256 + cb];
        Aqh[ks][2] = *(const uint32_t*)&qgh[(size_t)qrow*256 + cb + 8];
        Aqh[ks][3] = *(const uint32_t*)&qgh[(size_t)(qrow+8)*256 + cb + 8];
        Aql[ks][0] = *(const uint32_t*)&qgl[(size_t)qrow*256 + cb];
        Aql[ks][1] = *(const uint32_t*)&qgl[(size_t)(qrow+8)*256 + cb];
        Aql[ks][2] = *(const uint32_t*)&qgl[(size_t)qrow*256 + cb + 8];
        Aql[ks][3] = *(const uint32_t*)&qgl[(size_t)(qrow+8)*256 + cb + 8];
    }

    auto issue = [&](int ch, int st) {
        uint32_t base = smb + (uint32_t)(st*FSTAGE*2);
        int key0 = ch*128;
        int kr = t>>1, kc = (t&1)*32;
        const bf* skh = kgh + (size_t)(key0+kr)*256 + hcol + kc;
        const bf* skl = kgl + (size_t)(key0+kr)*256 + hcol + kc;
        #pragma unroll
        for (int i=0;i<4;i++) {
            uint32_t d = base + (uint32_t)((kr*KP + kc + i*8)*2);
            CP16(d,           skh + i*8);
            CP16(d + FK_L*2,  skl + i*8);
        }
        int vr = t>>2, vc = (t&3)*32;
        const bf* svh = vgh + (size_t)vr*2048 + key0 + vc;
        #pragma unroll
        for (int i=0;i<4;i++) {
            uint32_t d = base + (uint32_t)((FV_H + vr*VP + vc + i*8)*2);
            CP16(d, svh + i*8);
        }
        asm volatile("cp.async.commit_group;");
    };

    float m_run[2] = {-1e30f, -1e30f};
    float s_run[2] = {0.f, 0.f};
    float oacc[8][4] = {};
    int l15 = lane & 15, lhi = (lane >> 4)*8;

    issue(0, 0);
    for (int ch = 0; ch < 16; ch++) {
        int st = ch & 1;
        if (ch + 1 < 16) { issue(ch+1, st^1); asm volatile("cp.async.wait_group 1;"); }
        else             { asm volatile("cp.async.wait_group 0;"); }
        __syncthreads();
        uint32_t bKh = smb + (uint32_t)(st*FSTAGE*2);
        uint32_t bKl = bKh + FK_L*2;
        uint32_t bVh = bKh + FV_H*2;

        float sacc[16][4] = {};
        #pragma unroll
        for (int ks = 0; ks < 4; ks++) {
            #pragma unroll
            for (int j = 0; j < 16; j += 2) {
                uint32_t koff = (uint32_t)(((j*8 + l15)*KP + ks*16 + lhi)*2);
                uint32_t Bh[2][2], Bl[2][2];
                ldsm4(Bh[0][0],Bh[1][0],Bh[0][1],Bh[1][1], bKh + koff);
                ldsm4(Bl[0][0],Bl[1][0],Bl[0][1],Bl[1][1], bKl + koff);
                mma16816(sacc[j],   Aqh[ks], Bh[0]);
                mma16816(sacc[j],   Aqh[ks], Bl[0]);
                mma16816(sacc[j],   Aql[ks], Bh[0]);
                mma16816(sacc[j+1], Aqh[ks], Bh[1]);
                mma16816(sacc[j+1], Aqh[ks], Bl[1]);
                mma16816(sacc[j+1], Aql[ks], Bh[1]);
            }
        }
        float mx0 = -1e30f, mx1 = -1e30f;
        #pragma unroll
        for (int j = 0; j < 16; j++) {
            sacc[j][0]*=SC2; sacc[j][1]*=SC2; sacc[j][2]*=SC2; sacc[j][3]*=SC2;
            mx0 = fmaxf(mx0, fmaxf(sacc[j][0], sacc[j][1]));
            mx1 = fmaxf(mx1, fmaxf(sacc[j][2], sacc[j][3]));
        }
        mx0 = fmaxf(mx0, __shfl_xor_sync(0xffffffffu, mx0, 1));
        mx0 = fmaxf(mx0, __shfl_xor_sync(0xffffffffu, mx0, 2));
        mx1 = fmaxf(mx1, __shfl_xor_sync(0xffffffffu, mx1, 1));
        mx1 = fmaxf(mx1, __shfl_xor_sync(0xffffffffu, mx1, 2));
        float nm0 = fmaxf(m_run[0], mx0), nm1 = fmaxf(m_run[1], mx1);
        float al0 = exp2f(m_run[0]-nm0), al1 = exp2f(m_run[1]-nm1);
        float cs0 = 0.f, cs1 = 0.f;
        #pragma unroll
        for (int j = 0; j < 16; j++) {
            float p0=exp2f(sacc[j][0]-nm0), p1=exp2f(sacc[j][1]-nm0);
            float p2=exp2f(sacc[j][2]-nm1), p3=exp2f(sacc[j][3]-nm1);
            sacc[j][0]=p0; sacc[j][1]=p1; sacc[j][2]=p2; sacc[j][3]=p3;
            cs0 += p0+p1; cs1 += p2+p3;
        }
        cs0 += __shfl_xor_sync(0xffffffffu, cs0, 1);
        cs0 += __shfl_xor_sync(0xffffffffu, cs0, 2);
        cs1 += __shfl_xor_sync(0xffffffffu, cs1, 1);
        cs1 += __shfl_xor_sync(0xffffffffu, cs1, 2);
        s_run[0] = s_run[0]*al0 + cs0;
        s_run[1] = s_run[1]*al1 + cs1;
        m_run[0] = nm0; m_run[1] = nm1;
        #pragma unroll
        for (int j2 = 0; j2 < 8; j2++) {
            oacc[j2][0]*=al0; oacc[j2][1]*=al0; oacc[j2][2]*=al1; oacc[j2][3]*=al1;
        }
        #pragma unroll
        for (int kk = 0; kk < 8; kk++) {
            uint32_t Pah[4];
            Pah[0] = pkbf(sacc[2*kk  ][0], sacc[2*kk  ][1]);
            Pah[1] = pkbf(sacc[2*kk  ][2], sacc[2*kk  ][3]);
            Pah[2] = pkbf(sacc[2*kk+1][0], sacc[2*kk+1][1]);
            Pah[3] = pkbf(sacc[2*kk+1][2], sacc[2*kk+1][3]);
            #pragma unroll
            for (int j2 = 0; j2 < 8; j2 += 2) {
                uint32_t voff = (uint32_t)(((j2*8 + l15)*VP + kk*16 + lhi)*2);
                uint32_t Bh[2][2];
                ldsm4(Bh[0][0],Bh[1][0],Bh[0][1],Bh[1][1], bVh + voff);
                mma16816(oacc[j2],   Pah, Bh[0]);
                mma16816(oacc[j2+1], Pah, Bh[1]);
            }
        }
        __syncthreads();
    }
    float inv0 = 1.0f/s_run[0], inv1 = 1.0f/s_run[1];
    #pragma unroll
    for (int j2 = 0; j2 < 8; j2++) {
        int col = hcol + j2*8 + (lane&3)*2;
        uint32_t hi, lo;
        split2(oacc[j2][0]*inv0, oacc[j2][1]*inv0, hi, lo);
        *(uint32_t*)&outh[(size_t)qrow*256 + col] = hi;
        *(uint32_t*)&outl[(size_t)qrow*256 + col] = lo;
        split2(oacc[j2][2]*inv1, oacc[j2][3]*inv1, hi, lo);
        *(uint32_t*)&outh[(size_t)(qrow+8)*256 + col] = hi;
        *(uint32_t*)&outl[(size_t)(qrow+8)*256 + col] = lo;
    }
}

// ---------- fused one-time weight conversion ----------
#define WC_P  ((size_t)30*65536)
#define WC_M  ((size_t)10*65536)
#define WC_1  ((size_t)10*262144)
#define WC_2  ((size_t)10*131072)
#define WC_F  ((size_t)65536)
#define WC_TOT (WC_P+WC_M+WC_1+WC_2+WC_F)
__global__ void wconv_all(const float* __restrict__ pw, const float* __restrict__ mw,
                          const float* __restrict__ w1, const float* __restrict__ w2,
                          const float* __restrict__ fw,
                          bf* wqh, bf* wql, bf* wmh, bf* wml,
                          bf* w1h, bf* w1l, bf* w2h, bf* w2l, bf* fph, bf* fpl) {
    size_t idx = (size_t)blockIdx.x*256 + threadIdx.x;
    if (idx >= WC_TOT) return;
    bf *oh, *ol; size_t li;
    float v;
    if (idx < WC_P) {
        li = idx;
        int op=(li>>8)&255; int o=(op&63)*4+(op>>6);
        v = pw[(li & ~(size_t)0xFF00) | ((size_t)o<<8)];
        oh = wqh; ol = wql;
    } else if (idx < WC_P+WC_M) {
        li = idx - WC_P;
        int cp=li&255; int c=(cp&63)*4+(cp>>6);
        v = mw[(li & ~(size_t)0xFF) | (size_t)c];
        oh = wmh; ol = wml;
    } else if (idx < WC_P+WC_M+WC_1) {
        li = idx - WC_P - WC_M;
        v = w1[li]; oh = w1h; ol = w1l;
    } else if (idx < WC_P+WC_M+WC_1+WC_2) {
        li = idx - WC_P - WC_M - WC_1;
        v = w2[li]; oh = w2h; ol = w2l;
    } else {
        li = idx - WC_P - WC_M - WC_1 - WC_2;
        v = fw[li]; oh = fph; ol = fpl;
    }
    bf h = __float2bfloat16(v);
    oh[li]=h; ol[li]=__float2bfloat16(v-__bfloat162float(h));
}
__global__ void bias_perm(const float* __restrict__ pb, float* __restrict__ out) {
    int idx = blockIdx.x*256 + threadIdx.x;
    int op = idx & 255;
    out[idx] = pb[(idx & ~255) | ((op&63)*4 + (op>>6))];
}
struct TArgs { const float* in[2]; float* xF[2]; bf *yh[2], *yl[2]; };
__global__ void transpose_split(TArgs a) {
    __shared__ float tl[32][33];
    int zz = blockIdx.z, n0 = blockIdx.x*32, c0 = blockIdx.y*32;
    int tx = threadIdx.x&31, ty = threadIdx.x>>5;
    const float* in = a.in[zz];
    #pragma unroll
    for (int r=0;r<4;r++) tl[ty+r*8][tx] = in[(size_t)(c0+ty+r*8)*NN + n0+tx];
    __syncthreads();
    #pragma unroll
    for (int r=0;r<4;r++) {
        int n=n0+ty+r*8, c=c0+tx;
        float v = tl[tx][ty+r*8];
        a.xF[zz][(size_t)n*256+c]=v;
        bf h=__float2bfloat16(v);
        a.yh[zz][(size_t)n*512+c]=h;
        a.yl[zz][(size_t)n*512+c]=__float2bfloat16(v-__bfloat162float(h));
    }
}
__global__ void posenc_kernel(const float* __restrict__ kpts, const float* __restrict__ Wr,
                              float* __restrict__ cosv, float* __restrict__ sinv) {
    int idx = blockIdx.x*256 + threadIdx.x;
    if (idx >= NN*32) return;
    int p = idx & 31, n = idx >> 5;
    float kx = (kpts[2*n+0]-512.0f)*(1.0f/716.8f);
    float ky = (kpts[2*n+1]-384.0f)*(1.0f/716.8f);
    float pr = kx*Wr[2*p+0] + ky*Wr[2*p+1];
    cosv[idx] = cosf(pr); sinv[idx] = sinf(pr);
}
// ---------- batchnorm: full-grid two-pass ----------
__global__ void __launch_bounds__(256)
bn_stats(const float* __restrict__ hf, float* __restrict__ pS, float* __restrict__ pQ) {
    int z = blockIdx.z;
    size_t base = (size_t)z * HSZ;
    int l = threadIdx.x & 63, rr = threadIdx.x >> 6;
    int c = blockIdx.x*64 + l;
    int r0 = blockIdx.y*128;
    float su=0.f, sq=0.f;
    for (int n = r0+rr; n < r0+128; n += 4) {
        float x = hf[base + (size_t)n*512 + c];
        su += x; sq += x*x;
    }
    __shared__ float sS[4][64], sQ[4][64];
    sS[rr][l]=su; sQ[rr][l]=sq;
    __syncthreads();
    if (rr==0) {
        float S=0.f, Q=0.f;
        #pragma unroll
        for (int i=0;i<4;i++){ S+=sS[i][l]; Q+=sQ[i][l]; }
        int o = (z*16 + blockIdx.y)*512 + c;
        pS[o]=S; pQ[o]=Q;
    }
}
__global__ void __launch_bounds__(256)
bn_apply(const float* __restrict__ hf, const float* __restrict__ pS, const float* __restrict__ pQ,
         const float* __restrict__ g, const float* __restrict__ b,
         bf* __restrict__ oh, bf* __restrict__ ol) {
    int z = blockIdx.z;
    size_t base = (size_t)z * HSZ;
    __shared__ float sc[64], sh[64];
    int l = threadIdx.x & 63;
    if (threadIdx.x < 64) {
        int c = blockIdx.x*64 + threadIdx.x;
        float S=0.f, Q=0.f;
        #pragma unroll
        for (int k=0;k<16;k++){ S+=pS[(z*16+k)*512+c]; Q+=pQ[(z*16+k)*512+c]; }
        float mean=S*(1.0f/NN), var=Q*(1.0f/NN)-mean*mean;
        float s1=g[c]*rsqrtf(var+1e-5f);
        sc[threadIdx.x]=s1; sh[threadIdx.x]=b[c]-mean*s1;
    }
    __syncthreads();
    int c = blockIdx.x*64 + l;
    int rr = threadIdx.x >> 6, r0 = blockIdx.y*128;
    float s1=sc[l], s2=sh[l];
    for (int n = r0+rr; n < r0+128; n += 4) {
        float v=fmaxf(hf[base+(size_t)n*512+c]*s1+s2, 0.0f);
        bf h=__float2bfloat16(v);
        oh[base+(size_t)n*512+c]=h;
        ol[base+(size_t)n*512+c]=__float2bfloat16(v-__bfloat162float(h));
    }
}
// ---------- Sinkhorn (R13 structure; v_part 32 chunks) ----------
__global__ void bins_zero_kernel(float* __restrict__ C, const float* __restrict__ a,
                                 float* __restrict__ vv) {
    int i = blockIdx.x*256 + threadIdx.x;
    if (i >= NP1) return;
    float v = a[0];
    C[(size_t)i*NP1 + NN] = v;
    C[(size_t)NN*NP1 + i] = v;
    vv[i] = 0.0f;
}
__global__ void __launch_bounds__(256)
u_update_kernel(const float* __restrict__ C, const float* __restrict__ vv, float* __restrict__ u) {
    __shared__ float sm[8];
    int i = blockIdx.x;
    const float* row = C + (size_t)i*NP1;
    int t = threadIdx.x;
    float mx = -1e30f;
    for (int j=t; j<NP1; j+=256) mx = fmaxf(mx, row[j]+vv[j]);
    #pragma unroll
    for (int o=16;o>0;o>>=1) mx=fmaxf(mx,__shfl_xor_sync(0xffffffffu,mx,o));
    if ((t&31)==0) sm[t>>5]=mx;
    __syncthreads();
    mx=sm[0];
    #pragma unroll
    for (int w=1;w<8;w++) mx=fmaxf(mx,sm[w]);
    float s=0.f;
    for (int j=t; j<NP1; j+=256) s += __expf(row[j]+vv[j]-mx);
    #pragma unroll
    for (int o=16;o>0;o>>=1) s+=__shfl_xor_sync(0xffffffffu,s,o);
    __syncthreads();
    if ((t&31)==0) sm[t>>5]=s;
    __syncthreads();
    s=0.f;
    #pragma unroll
    for (int w=0;w<8;w++) s+=sm[w];
    if (t==0) u[i] = ((i<NN)?NORMC:(LOGN+NORMC)) - (mx + logf(s));
}
__global__ void v_part_kernel(const float* __restrict__ C, const float* __restrict__ u,
                              float* __restrict__ pm, float* __restrict__ ps) {
    int j = blockIdx.x*256 + threadIdx.x;
    if (j >= NP1) return;
    int rc = blockIdx.y, i0 = rc*65, i1 = min(i0+65, NP1);
    float m=-1e30f, s=0.f;
    for (int i=i0; i<i1; i++) {
        float x = C[(size_t)i*NP1+j] + u[i];
        if (x>m) { s=s*__expf(m-x)+1.f; m=x; } else s+=__expf(x-m);
    }
    pm[rc*NP1+j]=m; ps[rc*NP1+j]=s;
}
__global__ void v_combine_kernel(const float* __restrict__ pm, const float* __restrict__ ps,
                                 float* __restrict__ vv) {
    int j = blockIdx.x*256 + threadIdx.x;
    if (j >= NP1) return;
    float M=-1e30f;
    #pragma unroll
    for (int rc=0;rc<32;rc++) M=fmaxf(M, pm[rc*NP1+j]);
    float S=0.f;
    #pragma unroll
    for (int rc=0;rc<32;rc++) S+=ps[rc*NP1+j]*__expf(pm[rc*NP1+j]-M);
    vv[j] = ((j<NN)?NORMC:(LOGN+NORMC)) - (M + logf(S));
}
__global__ void final_add_kernel(float* __restrict__ C, const float* __restrict__ u,
                                 const float* __restrict__ vv) {
    int j = blockIdx.x*256 + threadIdx.x;
    int i = blockIdx.y;
    if (j >= NP1) return;
    C[(size_t)i*NP1 + j] += u[i] + vv[j] + LOG4096;
}

// ---------- host ----------
#define GSA(p,s) cudaGetSymbolAddress((void**)&(p), s)
extern "C" void kernel_launch(void* const* d_in, const int* in_sizes, int n_in,
                              void* d_out, int out_size) {
    (void)in_sizes; (void)n_in; (void)out_size;
    const float *desc0=(const float*)d_in[0], *desc1=(const float*)d_in[1];
    const float *kpts0=(const float*)d_in[2], *kpts1=(const float*)d_in[3];
    const float *Wr=(const float*)d_in[4], *proj_w=(const float*)d_in[5];
    const float *proj_b=(const float*)d_in[6];
    const float *merge_w=(const float*)d_in[7], *merge_b=(const float*)d_in[8];
    const float *mlp_w1=(const float*)d_in[9], *mlp_b1=(const float*)d_in[10];
    const float *bn_g=(const float*)d_in[11], *bn_b=(const float*)d_in[12];
    const float *mlp_w2=(const float*)d_in[13], *mlp_b2=(const float*)d_in[14];
    const float *fp_w=(const float*)d_in[15], *fp_b=(const float*)d_in[16];
    const float *binsc=(const float*)d_in[17];
    float* C = (float*)d_out;

    cudaFuncSetAttribute(mma_gemm<4>, cudaFuncAttributeMaxDynamicSharedMemorySize, SMEMB4);
    cudaFuncSetAttribute(mma_gemm<2>, cudaFuncAttributeMaxDynamicSharedMemorySize, SMEMB2);
    cudaFuncSetAttribute(flash_attn, cudaFuncAttributeMaxDynamicSharedMemorySize, FSMEM_B);

    float *xF,*hf,*pbp,*cs,*pu,*pvv,*ppm,*pps,*bnS,*bnQ;
    bf *yh,*yl,*qh,*ql,*kh,*kl,*vh,*vl,*aoh,*aol,*hh,*hl;
    bf *wqh,*wql,*wmh,*wml,*w1h,*w1l,*w2h,*w2l,*fph,*fpl;
    GSA(xF,g_xF); GSA(hf,g_hf);
    GSA(yh,g_yh); GSA(yl,g_yl); GSA(qh,g_qh); GSA(ql,g_ql);
    GSA(kh,g_kh); GSA(kl,g_kl); GSA(vh,g_vh); GSA(vl,g_vl);
    GSA(aoh,g_aoh); GSA(aol,g_aol); GSA(hh,g_hh); GSA(hl,g_hl);
    GSA(wqh,g_wqh); GSA(wql,g_wql); GSA(wmh,g_wmh); GSA(wml,g_wml);
    GSA(w1h,g_w1h); GSA(w1l,g_w1l); GSA(w2h,g_w2h); GSA(w2l,g_w2l);
    GSA(fph,g_fph); GSA(fpl,g_fpl); GSA(pbp,g_pbp); GSA(cs,g_cs);
    GSA(bnS,g_bnS); GSA(bnQ,g_bnQ);
    GSA(pu,g_u); GSA(pvv,g_vv); GSA(ppm,g_pm); GSA(pps,g_ps);
    float *c0=cs, *s0=cs+NN*32, *c1=cs+2*NN*32, *s1=cs+3*NN*32;

    wconv_all<<<(unsigned)((WC_TOT+255)/256),256>>>(proj_w, merge_w, mlp_w1, mlp_w2, fp_w,
                                                    wqh, wql, wmh, wml, w1h, w1l, w2h, w2l, fph, fpl);
    bias_perm<<<30,256>>>(proj_b, pbp);
    posenc_kernel<<<NN*32/256,256>>>(kpts0, Wr, c0, s0);
    posenc_kernel<<<NN*32/256,256>>>(kpts1, Wr, c1, s1);
    TArgs ta;
    ta.in[0]=desc0; ta.in[1]=desc1;
    for (int s=0;s<2;s++){ ta.xF[s]=xF+s*SZ; ta.yh[s]=yh+s*HSZ; ta.yl[s]=yl+s*HSZ; }
    transpose_split<<<dim3(64,8,2),256>>>(ta);

    for (int l=0; l<10; l++) {
        int even = !(l&1);
        int src[2] = { even?0:1, even?1:0 };
        const float* mb  = merge_b + l*256;
        const float* b1  = mlp_b1 + l*512;
        const float* b2  = mlp_b2 + l*256;
        const float* csv[2] = { c0, c1 };
        const float* snv[2] = { s0, s1 };

        // q,k projections with fused RoPE+split — JT=4
        MArgs mq = {};
        mq.lda=512; mq.ldb=256; mq.ldo=256; mq.ldh=256; mq.K=256; mq.Nc=256; mq.scale=1.f;
        for (int s=0;s<2;s++) {
            MZ* zq=&mq.z[s*2], *zk=&mq.z[s*2+1];
            zq->Ah=yh+s*HSZ; zq->Al=yl+s*HSZ;
            zq->Bh=wqh+(size_t)(l*3)*65536; zq->Bl=wql+(size_t)(l*3)*65536;
            zq->bias=pbp+(l*3)*256; zq->oh=qh+s*SZ; zq->ol=ql+s*SZ;
            zk->Ah=yh+src[s]*HSZ; zk->Al=yl+src[s]*HSZ;
            zk->Bh=wqh+(size_t)(l*3+1)*65536; zk->Bl=wql+(size_t)(l*3+1)*65536;
            zk->bias=pbp+(l*3+1)*256; zk->oh=kh+s*SZ; zk->ol=kl+s*SZ;
            if (even) {
                zq->cosv=csv[s]; zq->sinv=snv[s];
                zk->cosv=csv[s]; zk->sinv=snv[s];
            }
        }
        mma_gemm<4><<<dim3(16,2,4),256,SMEMB4>>>(mq);

        // v projection (transposed out) — JT=2
        MArgs mv = {};
        mv.lda=256; mv.ldb=512; mv.ldo=2048; mv.ldh=2048; mv.K=256; mv.Nc=2048;
        mv.scale=1.f; mv.bias_rows=1;
        for (int s=0;s<2;s++) {
            MZ* zv=&mv.z[s];
            zv->Ah=wqh+(size_t)(l*3+2)*65536; zv->Al=wql+(size_t)(l*3+2)*65536;
            zv->Bh=yh+src[s]*HSZ; zv->Bl=yl+src[s]*HSZ;
            zv->bias=pbp+(l*3+2)*256; zv->oh=vh+s*SZ; zv->ol=vl+s*SZ;
        }
        mma_gemm<2><<<dim3(2,32,2),256,SMEMB2>>>(mv);

        // fused attention
        flash_attn<<<dim3(16,8),256,FSMEM_B>>>(qh,ql,kh,kl,vh,aoh,aol);

        // merge -> y cols 256:511 — JT=2
        MArgs mm = {};
        mm.lda=256; mm.ldb=256; mm.ldh=512; mm.K=256; mm.Nc=256; mm.scale=1.f;
        for (int s=0;s<2;s++) {
            MZ* zz=&mm.z[s];
            zz->Ah=aoh+s*SZ; zz->Al=aol+s*SZ;
            zz->Bh=wmh+(size_t)l*65536; zz->Bl=wml+(size_t)l*65536;
            zz->bias=mb; zz->oh=yh+s*HSZ+256; zz->ol=yl+s*HSZ+256;
        }
        mma_gemm<2><<<dim3(16,4,2),256,SMEMB2>>>(mm);

        // mlp1 -> h fp32 — JT=4
        MArgs m1 = {};
        m1.lda=512; m1.ldb=512; m1.ldo=512; m1.K=512; m1.Nc=512; m1.scale=1.f;
        for (int s=0;s<2;s++) {
            MZ* zz=&m1.z[s];
            zz->Ah=yh+s*HSZ; zz->Al=yl+s*HSZ;
            zz->Bh=w1h+(size_t)l*262144; zz->Bl=w1l+(size_t)l*262144;
            zz->bias=b1; zz->outF=hf+s*HSZ;
        }
        mma_gemm<4><<<dim3(16,4,2),256,SMEMB4>>>(m1);
        bn_stats<<<dim3(8,16,2),256>>>(hf, bnS, bnQ);
        bn_apply<<<dim3(8,16,2),256>>>(hf, bnS, bnQ, bn_g+l*512, bn_b+l*512, hh, hl);

        // mlp2 + residual — JT=2
        MArgs m2 = {};
        m2.lda=512; m2.ldb=512; m2.ldo=256; m2.ldh=512; m2.K=512; m2.Nc=256; m2.scale=1.f;
        for (int s=0;s<2;s++) {
            MZ* zz=&m2.z[s];
            zz->Ah=hh+s*HSZ; zz->Al=hl+s*HSZ;
            zz->Bh=w2h+(size_t)l*131072; zz->Bl=w2l+(size_t)l*131072;
            zz->bias=b2; zz->res=xF+s*SZ; zz->outF=xF+s*SZ;
            zz->oh=yh+s*HSZ; zz->ol=yl+s*HSZ;
        }
        mma_gemm<2><<<dim3(16,4,2),256,SMEMB2>>>(m2);
    }

    // final projection — JT=2
    MArgs mf = {};
    mf.lda=512; mf.ldb=256; mf.ldh=256; mf.K=256; mf.Nc=256; mf.scale=1.f;
    for (int s=0;s<2;s++) {
        MZ* zz=&mf.z[s];
        zz->Ah=yh+s*HSZ; zz->Al=yl+s*HSZ;
        zz->Bh=fph; zz->Bl=fpl;
        zz->bias=fp_b; zz->oh=qh+s*SZ; zz->ol=ql+s*SZ;
    }
    mma_gemm<2><<<dim3(16,4,2),256,SMEMB2>>>(mf);

    // final match scores into C (ld 2049) — JT=4
    MArgs mc = {};
    mc.lda=256; mc.ldb=256; mc.ldo=NP1; mc.K=256; mc.Nc=2048; mc.scale=0.0625f;
    mc.z[0].Ah=qh; mc.z[0].Al=ql; mc.z[0].Bh=qh+SZ; mc.z[0].Bl=ql+SZ;
    mc.z[0].outF=C;
    mma_gemm<4><<<dim3(16,16,1),256,SMEMB4>>>(mc);
    bins_zero_kernel<<<(NP1+255)/256,256>>>(C, binsc, pvv);

    for (int t=0; t<20; t++) {
        u_update_kernel<<<NP1,256>>>(C, pvv, pu);
        v_part_kernel<<<dim3((NP1+255)/256,32),256>>>(C, pu, ppm, pps);
        v_combine_kernel<<<(NP1+255)/256,256>>>(ppm, pps, pvv);
    }
    final_add_kernel<<<dim3((NP1+255)/256, NP1),256>>>(C, pu, pvv);
}